// round 15
// baseline (speedup 1.0000x reference)
#include <cuda_runtime.h>
#include <cstdint>

// AUGRU: B=65536, T=50, E=10.
// Fold: (x@Wi + bi + h@Wh)@Ws + bs == x@(Wi@Ws) + h@(Wh@Ws) + (bi@Ws + bs)
// R14 = R13 (all weights + biases on the constant port, feature-packed f32x2
// dots, tanh.approx, cp.async double-buffered staging, no syncwarp) at
// ONE element per thread -> 2048 warps (3.46/SMSP) for latency coverage.
// Weight LDC per element doubles vs R13, but LDC rides the constant port,
// not L1 — the cost that killed the ept=1 variant in R8 is gone.

#define E_  10
#define T_  50
#define B_  65536
#define NB  32           // threads per block
#define EB  32           // batch elems per block (1 per thread)
#define RS  10           // floats per row per timestep
#define ROWB (T_*E_)     // 500 floats per batch row

// g_w2 layout (transposed A^T[j][k], row stride 12, 16B-aligned rows):
//   Axr@0, Axz@120, Axh@240, Ahr@360, Ahz@480, Ahh@600
//   biases: br@720, bz@730, bh@740
__device__ float g_w2[752];

// constant mirror of the whole weight set
__constant__ float c_w[752];

__global__ void augru_precompute(
    const float* __restrict__ Wi_r, const float* __restrict__ bi_r,
    const float* __restrict__ Wh_r, const float* __restrict__ Ws_r, const float* __restrict__ bs_r,
    const float* __restrict__ Wi_z, const float* __restrict__ bi_z,
    const float* __restrict__ Wh_z, const float* __restrict__ Ws_z, const float* __restrict__ bs_z,
    const float* __restrict__ Wi_h, const float* __restrict__ bi_h,
    const float* __restrict__ Wh_h, const float* __restrict__ Wt_h, const float* __restrict__ bt_h)
{
    int tid = threadIdx.x;
    if (tid < 600) {
        int m = tid / 100, rem = tid % 100, j = rem / 10, k = rem % 10;
        const float* W1; const float* W2; int dst;
        switch (m) {
            case 0: W1 = Wi_r; W2 = Ws_r; dst = 0;   break;  // Axr
            case 1: W1 = Wh_r; W2 = Ws_r; dst = 360; break;  // Ahr
            case 2: W1 = Wi_z; W2 = Ws_z; dst = 120; break;  // Axz
            case 3: W1 = Wh_z; W2 = Ws_z; dst = 480; break;  // Ahz
            case 4: W1 = Wi_h; W2 = Wt_h; dst = 240; break;  // Axh
            default: W1 = Wh_h; W2 = Wt_h; dst = 600; break; // Ahh
        }
        float acc = 0.f;
        #pragma unroll
        for (int mm = 0; mm < E_; mm++)
            acc += W1[k * E_ + mm] * W2[mm * E_ + j];
        g_w2[dst + j * 12 + k] = acc;
    } else if (tid < 630) {
        int g = (tid - 600) / 10, j = (tid - 600) % 10;
        const float* bi; const float* Ws; const float* bs;
        if (g == 0)      { bi = bi_r; Ws = Ws_r; bs = bs_r; }
        else if (g == 1) { bi = bi_z; Ws = Ws_z; bs = bs_z; }
        else             { bi = bi_h; Ws = Wt_h; bs = bt_h; }
        float acc = bs[j];
        #pragma unroll
        for (int mm = 0; mm < E_; mm++)
            acc += bi[mm] * Ws[mm * E_ + j];
        g_w2[720 + g * 10 + j] = acc;
    }
}

__device__ __forceinline__ float2 fma2(float2 a, float2 b, float2 c) {
    unsigned long long ua = *reinterpret_cast<unsigned long long*>(&a);
    unsigned long long ub = *reinterpret_cast<unsigned long long*>(&b);
    unsigned long long uc = *reinterpret_cast<unsigned long long*>(&c);
    unsigned long long ud;
    asm("fma.rn.f32x2 %0, %1, %2, %3;" : "=l"(ud) : "l"(ua), "l"(ub), "l"(uc));
    return *reinterpret_cast<float2*>(&ud);
}

__device__ __forceinline__ float tanh_ap(float x) {
    float y;
    asm("tanh.approx.f32 %0, %1;" : "=f"(y) : "f"(x));
    return y;
}
__device__ __forceinline__ float sigf(float x) {
    return fmaf(0.5f, tanh_ap(0.5f * x), 0.5f);
}

// one 10-float weight row, loaded once (f4,f4,f2) from the constant bank
struct W10 { float4 a; float4 b; float2 c; };

__device__ __forceinline__ W10 ldrow(const float* __restrict__ w) {
    W10 r;
    r.a = *reinterpret_cast<const float4*>(w);
    r.b = *reinterpret_cast<const float4*>(w + 4);
    r.c = *reinterpret_cast<const float2*>(w + 8);
    return r;
}

// dot of loaded row with feature-packed vector v[5] into (even,odd) acc
__device__ __forceinline__ float2 dotw(const W10& w, const float2* __restrict__ v, float2 acc) {
    acc = fma2(make_float2(w.a.x, w.a.y), v[0], acc);
    acc = fma2(make_float2(w.a.z, w.a.w), v[1], acc);
    acc = fma2(make_float2(w.b.x, w.b.y), v[2], acc);
    acc = fma2(make_float2(w.b.z, w.b.w), v[3], acc);
    acc = fma2(w.c,                       v[4], acc);
    return acc;
}

__device__ __forceinline__ void cpa8(uint32_t smem_addr, const void* gptr) {
    asm volatile("cp.async.ca.shared.global [%0], [%1], 8;" :: "r"(smem_addr), "l"(gptr));
}

__global__ void __launch_bounds__(NB) augru_main(
    const float* __restrict__ gx,   // [B, T, E]
    const float* __restrict__ ga,   // [B, T, E]
    const float* __restrict__ h0,   // [1, E]
    float* __restrict__ out)        // [B, E]
{
    __shared__ __align__(16) float sx[2][EB * RS];   // [buf][row][10]
    __shared__ __align__(16) float sa[2][EB * RS];

    const int tid = threadIdx.x;
    const int b0  = blockIdx.x * EB;

    const uint32_t sxa = (uint32_t)__cvta_generic_to_shared(&sx[0][0]);
    const uint32_t saa = (uint32_t)__cvta_generic_to_shared(&sa[0][0]);
    const char* gxb = (const char*)gx + (size_t)b0 * (ROWB * 4);
    const char* gab = (const char*)ga + (size_t)b0 * (ROWB * 4);

    // stage timestep t into buffer d: each thread copies its own row (5 x 8B)
    auto stage = [&](int t, int d) {
        const int tb = t * (RS * 4);
        const uint32_t sbase = (uint32_t)((d * (EB * RS) + tid * RS) * 4);
        const size_t gbase = (size_t)tid * (ROWB * 4) + tb;
        #pragma unroll
        for (int c = 0; c < 5; c++) {
            cpa8(sxa + sbase + c * 8, gxb + gbase + c * 8);
            cpa8(saa + sbase + c * 8, gab + gbase + c * 8);
        }
        asm volatile("cp.async.commit_group;");
    };

    stage(0, 0);

    // h feature-packed: h[i] = (h_{2i}, h_{2i+1}) of this thread's batch row
    float2 h[5];
    #pragma unroll
    for (int i = 0; i < 5; i++) h[i] = make_float2(h0[2 * i], h0[2 * i + 1]);

    #pragma unroll 1
    for (int t = 0; t < T_; t++) {
        const int d = t & 1;
        if (t + 1 < T_) {
            stage(t + 1, d ^ 1);
            asm volatile("cp.async.wait_group 1;");
        } else {
            asm volatile("cp.async.wait_group 0;");
        }
        // no __syncwarp(): each thread reads only the row it staged itself.

        const float* __restrict__ xr = &sx[d][tid * RS];
        const float* __restrict__ ar = &sa[d][tid * RS];

        // x features, naturally packed (40B rows, 8B-aligned)
        float2 xp[5];
        #pragma unroll
        for (int i = 0; i < 5; i++)
            xp[i] = *reinterpret_cast<const float2*>(xr + 2 * i);

        // ---- loop 1: rp, zp pre-activations ----
        float rp[E_], zp[E_];
        #pragma unroll
        for (int j = 0; j < E_; j++) {
            W10 wxr = ldrow(c_w + 0   + j * 12);
            W10 whr = ldrow(c_w + 360 + j * 12);
            W10 wxz = ldrow(c_w + 120 + j * 12);
            W10 whz = ldrow(c_w + 480 + j * 12);
            float2 r = make_float2(c_w[720 + j], 0.f);
            float2 z = make_float2(c_w[730 + j], 0.f);
            r = dotw(wxr, xp, r);
            r = dotw(whr, h,  r);
            z = dotw(wxz, xp, z);
            z = dotw(whz, h,  z);
            rp[j] = r.x + r.y;
            zp[j] = z.x + z.y;
        }

        // ---- loop 2: hz = h * sigmoid(zp) ----
        float2 hz[5];
        #pragma unroll
        for (int i = 0; i < 5; i++)
            hz[i] = make_float2(h[i].x * sigf(zp[2 * i]),
                                h[i].y * sigf(zp[2 * i + 1]));

        // ---- loop 3: candidate pre-activation ----
        float hcp[E_];
        #pragma unroll
        for (int j = 0; j < E_; j++) {
            W10 wxh = ldrow(c_w + 240 + j * 12);
            W10 whh = ldrow(c_w + 600 + j * 12);
            float2 c = make_float2(c_w[740 + j], 0.f);
            c = dotw(wxh, xp, c);
            c = dotw(whh, hz, c);
            hcp[j] = c.x + c.y;
        }

        // ---- loop 4: blend ----
        #pragma unroll
        for (int i = 0; i < 5; i++) {
            float2 ap = *reinterpret_cast<const float2*>(ar + 2 * i);
            float Ra0 = ap.x * sigf(rp[2 * i]);
            float Ra1 = ap.y * sigf(rp[2 * i + 1]);
            float hc0 = tanh_ap(hcp[2 * i]);
            float hc1 = tanh_ap(hcp[2 * i + 1]);
            h[i].x = fmaf(Ra0, hc0 - h[i].x, h[i].x);
            h[i].y = fmaf(Ra1, hc1 - h[i].y, h[i].y);
        }
    }

    // write out: this thread's row, 5 float2
    float2* __restrict__ po = reinterpret_cast<float2*>(out) + (size_t)(b0 + tid) * 5;
    #pragma unroll
    for (int i = 0; i < 5; i++) po[i] = h[i];
}

extern "C" void kernel_launch(void* const* d_in, const int* in_sizes, int n_in,
                              void* d_out, int out_size) {
    const float* gx   = (const float*)d_in[0];
    const float* ga   = (const float*)d_in[1];
    const float* h0   = (const float*)d_in[2];
    const float* Wi_r = (const float*)d_in[3];
    const float* bi_r = (const float*)d_in[4];
    const float* Wh_r = (const float*)d_in[5];
    const float* Ws_r = (const float*)d_in[6];
    const float* bs_r = (const float*)d_in[7];
    const float* Wi_z = (const float*)d_in[8];
    const float* bi_z = (const float*)d_in[9];
    const float* Wh_z = (const float*)d_in[10];
    const float* Ws_z = (const float*)d_in[11];
    const float* bs_z = (const float*)d_in[12];
    const float* Wi_h = (const float*)d_in[13];
    const float* bi_h = (const float*)d_in[14];
    const float* Wh_h = (const float*)d_in[15];
    const float* Wt_h = (const float*)d_in[16];
    const float* bt_h = (const float*)d_in[17];
    float* out = (float*)d_out;

    augru_precompute<<<1, 640>>>(Wi_r, bi_r, Wh_r, Ws_r, bs_r,
                                 Wi_z, bi_z, Wh_z, Ws_z, bs_z,
                                 Wi_h, bi_h, Wh_h, Wt_h, bt_h);

    void* g_ptr = nullptr;
    cudaGetSymbolAddress(&g_ptr, g_w2);
    cudaMemcpyToSymbolAsync(c_w, g_ptr, 752 * sizeof(float), 0,
                            cudaMemcpyDeviceToDevice, 0);

    augru_main<<<B_ / EB, NB>>>(gx, ga, h0, out);
}